// round 7
// baseline (speedup 1.0000x reference)
#include <cuda_runtime.h>

// image2patch: input (32,8,256,256) f32 -> out (256, 3969, 64) f32
// 63x63 patch grid per image (stride 4, patch 8x8), patch rows are
// 4-float aligned -> pure float4 copy kernel.
//
// Per image: 3969 patches * 16 float4 each.
// Block = 256 threads = 16 patches; tid>>4 selects patch-in-block,
// tid&15 selects the float4 within the 64-float patch.

#define N_PATCHES   3969   // 63*63
#define PATCH_F4    16     // 64 floats / 4
#define ROW_F4      64     // 256 floats per image row / 4
#define IMG_F4      16384  // 256*256 / 4

__global__ __launch_bounds__(256, 8)
void image2patch_kernel(const float4* __restrict__ in, float4* __restrict__ out) {
    const int tid = threadIdx.x;
    const int k4  = tid & (PATCH_F4 - 1);          // 0..15: float4 index within patch
    const int p   = blockIdx.x * 16 + (tid >> 4);  // patch index within image
    if (p >= N_PATCHES) return;
    const int img = blockIdx.y;                    // 0..255

    const int pr = p / 63;                         // patch row  (magic-mul)
    const int pc = p - pr * 63;                    // patch col

    const int r  = pr * 4 + (k4 >> 1);             // source pixel row (0..255)
    const int c4 = pc + (k4 & 1);                  // source col in float4 units (0..63)

    const float4 v = in[img * IMG_F4 + r * ROW_F4 + c4];

    out[(img * N_PATCHES + p) * PATCH_F4 + k4] = v;
}

extern "C" void kernel_launch(void* const* d_in, const int* in_sizes, int n_in,
                              void* d_out, int out_size) {
    const float4* in  = (const float4*)d_in[0];
    float4*       out = (float4*)d_out;

    // 3969 patches / 16 per block = 249 blocks (last block partially masked)
    dim3 grid((N_PATCHES + 15) / 16, 256, 1);   // y = B*C images
    dim3 block(256, 1, 1);
    image2patch_kernel<<<grid, block>>>(in, out);
}

// round 8
// speedup vs baseline: 1.3800x; 1.3800x over previous
#include <cuda_runtime.h>

// image2patch via smem staging: input (256 imgs, 256, 256) f32 ->
// out (256, 3969, 64) f32. Patch grid 63x63 (stride 4, patch 8x8).
//
// Block = (img, patch_row). Stage the 8-row x 256-col band into smem
// with coalesced LDG.128, then write the 63 patches (1008 float4,
// fully contiguous) with coalesced STG.128. Scatter happens in smem.
//
// smem row stride 66 float4: LDS.128 quarter-warp addr mod 8 =
// (2r + pc + b) mod 8 -> all 8 bank-groups distinct -> conflict-free.

#define N_PR        63
#define N_PC        63
#define N_PATCHES   3969    // 63*63
#define ROW_F4      64      // 256 floats / 4
#define IMG_F4      16384   // 256*256 / 4
#define SROW        66      // smem row stride in float4 (padded)
#define OUT_F4      1008    // 63 patches * 16 float4

__global__ __launch_bounds__(256, 8)
void image2patch_kernel(const float4* __restrict__ in, float4* __restrict__ out) {
    __shared__ float4 s[8 * SROW];   // 8448 B

    const int tid = threadIdx.x;
    const int pr  = blockIdx.x;      // 0..62
    const int img = blockIdx.y;      // 0..255

    // ---- Load phase: 8 rows x 64 float4, coalesced ----
    const float4* src = in + img * IMG_F4 + (pr * 4) * ROW_F4;
    {
        int idx = tid;                       // 0..255
        int row = idx >> 6, c4 = idx & 63;
        s[row * SROW + c4] = src[row * ROW_F4 + c4];
        idx += 256;                          // 256..511
        row = idx >> 6; c4 = idx & 63;
        s[row * SROW + c4] = src[row * ROW_F4 + c4];
    }
    __syncthreads();

    // ---- Store phase: 1008 contiguous float4, coalesced ----
    float4* dst = out + (img * N_PATCHES + pr * N_PC) * 16;
    #pragma unroll
    for (int i = 0; i < 4; i++) {
        const int q = tid + i * 256;         // 0..1023
        if (q < OUT_F4) {
            const int pc = q >> 4;           // patch col 0..62
            const int k4 = q & 15;           // float4 within patch
            const int r  = k4 >> 1;          // row in band 0..7
            const int b  = k4 & 1;           // col half
            dst[q] = s[r * SROW + pc + b];
        }
    }
}

extern "C" void kernel_launch(void* const* d_in, const int* in_sizes, int n_in,
                              void* d_out, int out_size) {
    const float4* in  = (const float4*)d_in[0];
    float4*       out = (float4*)d_out;

    dim3 grid(N_PR, 256, 1);   // (patch_row, image)
    dim3 block(256, 1, 1);
    image2patch_kernel<<<grid, block>>>(in, out);
}